// round 4
// baseline (speedup 1.0000x reference)
#include <cuda_runtime.h>
#include <cstdint>
#include <math.h>

// ---------------- problem constants ----------------
#define BS_      16
#define LQ_      1000
#define NROWS    (BS_*LQ_)         // 16000
#define EMBED    256
#define NHEADS   8
#define SUMP     16
#define HDIM     32
#define NLOGIT   384               // 256 offset cols + 128 attn cols
#define LV_      13294

__device__ float g_logits[NROWS * NLOGIT];   // scratch: off(256) | attn(128) per row

// ---------------- Kernel A: fused SGEMM  C[16000,384] = Q[16000,256] @ [W_off|W_attn] + bias ----------------
#define BM 64
#define BN 128
#define BKK 8
#define TM 8
#define TN 8

__global__ __launch_bounds__(128, 5)
void gemm_kernel(const float* __restrict__ Q,
                 const float* __restrict__ Woff,
                 const float* __restrict__ Wattn,
                 const float* __restrict__ boff,
                 const float* __restrict__ battn)
{
    __shared__ float As[BKK][BM];
    __shared__ float Bs[BKK][BN];

    const int bm = blockIdx.x;           // 0..249
    const int bn = blockIdx.y;           // 0..2

    const float* Bsrc;
    int ldb;
    const float* bias;
    if (bn < 2) { Bsrc = Woff + bn * 128; ldb = 256; bias = boff + bn * 128; }
    else        { Bsrc = Wattn;           ldb = 128; bias = battn; }

    const float* A = Q + (size_t)bm * BM * EMBED;

    const int tid  = threadIdx.x;        // 0..127
    const int tcol = tid & 15;           // 0..15 (BN/TN)
    const int trow = tid >> 4;           // 0..7  (BM/TM)

    const int arow = tid >> 1;           // 0..63
    const int acol = (tid & 1) * 4;      // 0 or 4
    const int brow = tid >> 4;           // 0..7
    const int bcol = (tid & 15) * 4;     // 0..60

    float acc[TM][TN];
    #pragma unroll
    for (int i = 0; i < TM; i++)
        #pragma unroll
        for (int j = 0; j < TN; j++) acc[i][j] = 0.f;

    for (int k0 = 0; k0 < EMBED; k0 += BKK) {
        float4 av = *reinterpret_cast<const float4*>(A + (size_t)arow * EMBED + k0 + acol);
        As[acol + 0][arow] = av.x;
        As[acol + 1][arow] = av.y;
        As[acol + 2][arow] = av.z;
        As[acol + 3][arow] = av.w;
        float4 bv0 = *reinterpret_cast<const float4*>(Bsrc + (size_t)(k0 + brow) * ldb + bcol);
        float4 bv1 = *reinterpret_cast<const float4*>(Bsrc + (size_t)(k0 + brow) * ldb + bcol + 64);
        *reinterpret_cast<float4*>(&Bs[brow][bcol])      = bv0;
        *reinterpret_cast<float4*>(&Bs[brow][bcol + 64]) = bv1;
        __syncthreads();

        #pragma unroll
        for (int kk = 0; kk < BKK; kk++) {
            float4 a0 = *reinterpret_cast<const float4*>(&As[kk][trow * TM]);
            float4 a1 = *reinterpret_cast<const float4*>(&As[kk][trow * TM + 4]);
            float4 b0 = *reinterpret_cast<const float4*>(&Bs[kk][tcol * TN]);
            float4 b1 = *reinterpret_cast<const float4*>(&Bs[kk][tcol * TN + 4]);
            float ar[TM] = {a0.x, a0.y, a0.z, a0.w, a1.x, a1.y, a1.z, a1.w};
            float br[TN] = {b0.x, b0.y, b0.z, b0.w, b1.x, b1.y, b1.z, b1.w};
            #pragma unroll
            for (int i = 0; i < TM; i++)
                #pragma unroll
                for (int j = 0; j < TN; j++)
                    acc[i][j] = fmaf(ar[i], br[j], acc[i][j]);
        }
        __syncthreads();
    }

    float bv[TN];
    #pragma unroll
    for (int j = 0; j < TN; j++) bv[j] = bias[tcol * TN + j];

    #pragma unroll
    for (int i = 0; i < TM; i++) {
        int row = bm * BM + trow * TM + i;
        float* op = g_logits + (size_t)row * NLOGIT + bn * 128 + tcol * TN;
        float4 o0, o1;
        o0.x = acc[i][0] + bv[0]; o0.y = acc[i][1] + bv[1];
        o0.z = acc[i][2] + bv[2]; o0.w = acc[i][3] + bv[3];
        o1.x = acc[i][4] + bv[4]; o1.y = acc[i][5] + bv[5];
        o1.z = acc[i][6] + bv[6]; o1.w = acc[i][7] + bv[7];
        *reinterpret_cast<float4*>(op)     = o0;
        *reinterpret_cast<float4*>(op + 4) = o1;
    }
}

// ---------------- Kernel B: softmax + bilinear sampling ----------------
// one warp per (b, h, q). Gather layout: psub = lane>>3 selects one of 4 points
// (same level) handled in parallel; dgrp = lane&7 covers the 32-dim head with
// float4 loads. Each lane recomputes its own point's coordinates from a
// broadcast LDG.64 (no cross-lane shuffles on the critical path); all weights
// and addresses are pre-staged so the 16 corner loads can batch (high MLP).

__global__ __launch_bounds__(256, 4)
void sample_kernel(const float* __restrict__ value,
                   const float* __restrict__ refp,
                   float* __restrict__ out)
{
    constexpr int cW[4]  = {100, 50, 25, 13};
    constexpr int cVS[4] = {0, 10000, 12500, 13125};

    const int warp = (blockIdx.x << 3) + (threadIdx.x >> 5);   // 0..127999
    const int lane = threadIdx.x & 31;

    const int q  = warp % LQ_;
    const int bh = warp / LQ_;
    const int b  = bh >> 3;
    const int h  = bh & 7;
    const int row = b * LQ_ + q;

    const float* lg = g_logits + (size_t)row * NLOGIT;
    const float4 rp = __ldg(reinterpret_cast<const float4*>(refp) + row);

    // ---- softmax over 16 attn logits (lanes 0..15 hold them) ----
    float logit = (lane < 16) ? __ldg(lg + 256 + h * 16 + lane) : -INFINITY;
    float m = logit;
    #pragma unroll
    for (int o = 16; o; o >>= 1) m = fmaxf(m, __shfl_xor_sync(0xffffffffu, m, o));
    float e = (lane < 16) ? __expf(logit - m) : 0.f;
    float s = e;
    #pragma unroll
    for (int o = 16; o; o >>= 1) s += __shfl_xor_sync(0xffffffffu, s, o);
    const float a = e / s;

    // ---- gather phase ----
    const int psub = lane >> 3;     // 0..3 : which point within the level
    const int dgrp = lane & 7;      // 0..7 : which float4 of the 32-dim head

    // per-lane point offsets: all 16 points' (x,y) pairs sit in ONE 128B line
    const float2* offp = reinterpret_cast<const float2*>(lg) + h * 16 + psub;
    float2 off[4];
    #pragma unroll
    for (int it = 0; it < 4; it++) off[it] = __ldg(offp + (it << 2));

    // pre-stage weights / integer coords / base offsets for all 4 iterations
    float wq[4][4];
    int   xx0[4], yy0[4];
    long  boff_[4];
    #pragma unroll
    for (int it = 0; it < 4; it++) {
        const float Wf = (float)cW[it];
        const float px = fmaf(fmaf(off[it].x, 0.125f * rp.z, rp.x), Wf, -0.5f);
        const float py = fmaf(fmaf(off[it].y, 0.125f * rp.w, rp.y), Wf, -0.5f);
        const float fx0 = floorf(px), fy0 = floorf(py);
        const float fx = px - fx0,    fy = py - fy0;
        xx0[it] = (int)fx0;
        yy0[it] = (int)fy0;

        const float ap = __shfl_sync(0xffffffffu, a, (it << 2) + psub);
        const float gx = 1.f - fx, gy = 1.f - fy;
        wq[it][0] = ap * gx * gy;
        wq[it][1] = ap * fx * gy;
        wq[it][2] = ap * gx * fy;
        wq[it][3] = ap * fx * fy;

        boff_[it] = (long)cVS[it] * EMBED + (long)(yy0[it] * cW[it] + xx0[it]) * EMBED;
    }

    const float* vb = value + (size_t)b * LV_ * EMBED + h * HDIM + dgrp * 4;

    float4 acc0 = make_float4(0.f, 0.f, 0.f, 0.f);
    float4 acc1 = acc0;

    #pragma unroll
    for (int it = 0; it < 4; it++) {
        const int W = cW[it];
        const int x0 = xx0[it], y0 = yy0[it];
        const bool xin0 = (unsigned)x0       < (unsigned)W;
        const bool xin1 = (unsigned)(x0 + 1) < (unsigned)W;
        const bool yin0 = (unsigned)y0       < (unsigned)W;   // H == W
        const bool yin1 = (unsigned)(y0 + 1) < (unsigned)W;

        const float* vl = vb + boff_[it];

        float4 v00 = make_float4(0.f,0.f,0.f,0.f);
        float4 v10 = v00, v01 = v00, v11 = v00;
        if (xin0 && yin0) v00 = *reinterpret_cast<const float4*>(vl);
        if (xin1 && yin0) v10 = *reinterpret_cast<const float4*>(vl + EMBED);
        if (xin0 && yin1) v01 = *reinterpret_cast<const float4*>(vl + W * EMBED);
        if (xin1 && yin1) v11 = *reinterpret_cast<const float4*>(vl + W * EMBED + EMBED);

        const float w00 = wq[it][0], w10 = wq[it][1];
        const float w01 = wq[it][2], w11 = wq[it][3];

        float4& acc = (it & 1) ? acc1 : acc0;
        acc.x = fmaf(w00, v00.x, fmaf(w10, v10.x, fmaf(w01, v01.x, fmaf(w11, v11.x, acc.x))));
        acc.y = fmaf(w00, v00.y, fmaf(w10, v10.y, fmaf(w01, v01.y, fmaf(w11, v11.y, acc.y))));
        acc.z = fmaf(w00, v00.z, fmaf(w10, v10.z, fmaf(w01, v01.z, fmaf(w11, v11.z, acc.z))));
        acc.w = fmaf(w00, v00.w, fmaf(w10, v10.w, fmaf(w01, v01.w, fmaf(w11, v11.w, acc.w))));
    }

    float4 acc;
    acc.x = acc0.x + acc1.x;
    acc.y = acc0.y + acc1.y;
    acc.z = acc0.z + acc1.z;
    acc.w = acc0.w + acc1.w;

    // ---- reduce over the 4 point-slots (lanes xor 8 and 16) ----
    #pragma unroll
    for (int o = 8; o <= 16; o <<= 1) {
        acc.x += __shfl_xor_sync(0xffffffffu, acc.x, o);
        acc.y += __shfl_xor_sync(0xffffffffu, acc.y, o);
        acc.z += __shfl_xor_sync(0xffffffffu, acc.z, o);
        acc.w += __shfl_xor_sync(0xffffffffu, acc.w, o);
    }

    if (psub == 0) {
        *reinterpret_cast<float4*>(out + (size_t)row * EMBED + h * HDIM + dgrp * 4) = acc;
    }
}

// ---------------- launch ----------------
extern "C" void kernel_launch(void* const* d_in, const int* in_sizes, int n_in,
                              void* d_out, int out_size)
{
    const float* query = (const float*)d_in[0];
    const float* refp  = (const float*)d_in[1];
    const float* value = (const float*)d_in[2];
    // d_in[3] = value_spatial_shapes (int64) — hardcoded
    const float* Woff  = (const float*)d_in[4];
    const float* boff  = (const float*)d_in[5];
    const float* Wattn = (const float*)d_in[6];
    const float* battn = (const float*)d_in[7];
    float* out = (float*)d_out;

    dim3 g(NROWS / BM, NLOGIT / BN);   // (250, 3)
    gemm_kernel<<<g, 128>>>(query, Woff, Wattn, boff, battn);

    sample_kernel<<<(BS_ * NHEADS * LQ_) / 8, 256>>>(value, refp, out);
}

// round 5
// speedup vs baseline: 1.0958x; 1.0958x over previous
#include <cuda_runtime.h>
#include <cstdint>
#include <math.h>

// ---------------- problem constants ----------------
#define BS_      16
#define LQ_      1000
#define NROWS    (BS_*LQ_)         // 16000
#define EMBED    256
#define NHEADS   8
#define SUMP     16
#define HDIM     32
#define NLOGIT   384               // 256 offset cols + 128 attn-prob cols
#define LV_      13294

__device__ float g_logits[NROWS * NLOGIT];   // scratch: off(256) | softmaxed attn(128)

// ---------------- Kernel A: fused SGEMM + softmax epilogue ----------------
// C[16000,384] = Q[16000,256] @ [W_off | W_attn] + bias.
// For the attn block (bn==2) the epilogue applies the per-head 16-way softmax
// in-register: thread tcol and its partner tcol^1 together hold one head's 16
// logits for each of the 8 rows -> one shfl_xor for max, one for sum.
#define BM 64
#define BN 128
#define BKK 8
#define TM 8
#define TN 8

__global__ __launch_bounds__(128, 5)
void gemm_kernel(const float* __restrict__ Q,
                 const float* __restrict__ Woff,
                 const float* __restrict__ Wattn,
                 const float* __restrict__ boff,
                 const float* __restrict__ battn)
{
    __shared__ float As[BKK][BM];
    __shared__ float Bs[BKK][BN];

    const int bm = blockIdx.x;           // 0..249
    const int bn = blockIdx.y;           // 0..2

    const float* Bsrc;
    int ldb;
    const float* bias;
    if (bn < 2) { Bsrc = Woff + bn * 128; ldb = 256; bias = boff + bn * 128; }
    else        { Bsrc = Wattn;           ldb = 128; bias = battn; }

    const float* A = Q + (size_t)bm * BM * EMBED;

    const int tid  = threadIdx.x;        // 0..127
    const int tcol = tid & 15;           // 0..15 (BN/TN)
    const int trow = tid >> 4;           // 0..7  (BM/TM)

    const int arow = tid >> 1;           // 0..63
    const int acol = (tid & 1) * 4;      // 0 or 4
    const int brow = tid >> 4;           // 0..7
    const int bcol = (tid & 15) * 4;     // 0..60

    float acc[TM][TN];
    #pragma unroll
    for (int i = 0; i < TM; i++)
        #pragma unroll
        for (int j = 0; j < TN; j++) acc[i][j] = 0.f;

    for (int k0 = 0; k0 < EMBED; k0 += BKK) {
        float4 av = *reinterpret_cast<const float4*>(A + (size_t)arow * EMBED + k0 + acol);
        As[acol + 0][arow] = av.x;
        As[acol + 1][arow] = av.y;
        As[acol + 2][arow] = av.z;
        As[acol + 3][arow] = av.w;
        float4 bv0 = *reinterpret_cast<const float4*>(Bsrc + (size_t)(k0 + brow) * ldb + bcol);
        float4 bv1 = *reinterpret_cast<const float4*>(Bsrc + (size_t)(k0 + brow) * ldb + bcol + 64);
        *reinterpret_cast<float4*>(&Bs[brow][bcol])      = bv0;
        *reinterpret_cast<float4*>(&Bs[brow][bcol + 64]) = bv1;
        __syncthreads();

        #pragma unroll
        for (int kk = 0; kk < BKK; kk++) {
            float4 a0 = *reinterpret_cast<const float4*>(&As[kk][trow * TM]);
            float4 a1 = *reinterpret_cast<const float4*>(&As[kk][trow * TM + 4]);
            float4 b0 = *reinterpret_cast<const float4*>(&Bs[kk][tcol * TN]);
            float4 b1 = *reinterpret_cast<const float4*>(&Bs[kk][tcol * TN + 4]);
            float ar[TM] = {a0.x, a0.y, a0.z, a0.w, a1.x, a1.y, a1.z, a1.w};
            float br[TN] = {b0.x, b0.y, b0.z, b0.w, b1.x, b1.y, b1.z, b1.w};
            #pragma unroll
            for (int i = 0; i < TM; i++)
                #pragma unroll
                for (int j = 0; j < TN; j++)
                    acc[i][j] = fmaf(ar[i], br[j], acc[i][j]);
        }
        __syncthreads();
    }

    float bv[TN];
    #pragma unroll
    for (int j = 0; j < TN; j++) bv[j] = bias[tcol * TN + j];

    #pragma unroll
    for (int i = 0; i < TM; i++)
        #pragma unroll
        for (int j = 0; j < TN; j++)
            acc[i][j] += bv[j];

    if (bn == 2) {
        // per-head softmax: this thread's 8 cols + partner (tid^1) = one head's 16
        #pragma unroll
        for (int i = 0; i < TM; i++) {
            float m8 = acc[i][0];
            #pragma unroll
            for (int j = 1; j < TN; j++) m8 = fmaxf(m8, acc[i][j]);
            float m16 = fmaxf(m8, __shfl_xor_sync(0xffffffffu, m8, 1));
            float s8 = 0.f;
            #pragma unroll
            for (int j = 0; j < TN; j++) {
                acc[i][j] = __expf(acc[i][j] - m16);
                s8 += acc[i][j];
            }
            float s16 = s8 + __shfl_xor_sync(0xffffffffu, s8, 1);
            float r = __fdividef(1.f, s16);
            #pragma unroll
            for (int j = 0; j < TN; j++) acc[i][j] *= r;
        }
    }

    #pragma unroll
    for (int i = 0; i < TM; i++) {
        int row = bm * BM + trow * TM + i;
        float* op = g_logits + (size_t)row * NLOGIT + bn * 128 + tcol * TN;
        float4 o0, o1;
        o0.x = acc[i][0]; o0.y = acc[i][1]; o0.z = acc[i][2]; o0.w = acc[i][3];
        o1.x = acc[i][4]; o1.y = acc[i][5]; o1.z = acc[i][6]; o1.w = acc[i][7];
        *reinterpret_cast<float4*>(op)     = o0;
        *reinterpret_cast<float4*>(op + 4) = o1;
    }
}

// ---------------- Kernel B: bilinear sampling (shuffle-free gather) ----------------
// one warp per (b, h, q). psub = lane>>3 selects one of 4 points (same level)
// handled in parallel; dgrp = lane&7 covers the 32-dim head with float4 loads.
// Each lane loads its own point's offset pair and (pre-softmaxed) probability
// directly (both from single 128B lines) and recomputes coordinates locally —
// no cross-lane shuffles until the final reduction.

__global__ __launch_bounds__(256, 6)
void sample_kernel(const float* __restrict__ value,
                   const float* __restrict__ refp,
                   float* __restrict__ out)
{
    constexpr int cW[4]  = {100, 50, 25, 13};
    constexpr int cVS[4] = {0, 10000, 12500, 13125};

    const int warp = (blockIdx.x << 3) + (threadIdx.x >> 5);   // 0..127999
    const int lane = threadIdx.x & 31;

    const int q  = warp % LQ_;
    const int bh = warp / LQ_;
    const int b  = bh >> 3;
    const int h  = bh & 7;
    const int row = b * LQ_ + q;

    const float* lg = g_logits + (size_t)row * NLOGIT;
    const float4 rp = __ldg(reinterpret_cast<const float4*>(refp) + row);

    const int psub = lane >> 3;     // 0..3 : which point within the level
    const int dgrp = lane & 7;      // 0..7 : which float4 of the 32-dim head

    // per-lane point data: all within one 128B line each
    const float2* offp = reinterpret_cast<const float2*>(lg) + h * 16 + psub;
    const float*  app  = lg + 256 + h * 16 + psub;

    float2 off[4];
    float  ap[4];
    #pragma unroll
    for (int it = 0; it < 4; it++) {
        off[it] = __ldg(offp + (it << 2));
        ap[it]  = __ldg(app  + (it << 2));
    }

    const float* vb = value + (size_t)b * LV_ * EMBED + h * HDIM + dgrp * 4;

    float4 acc0 = make_float4(0.f, 0.f, 0.f, 0.f);
    float4 acc1 = acc0;

    #pragma unroll
    for (int it = 0; it < 4; it++) {
        const int   W  = cW[it];
        const float Wf = (float)W;

        const float px = fmaf(fmaf(off[it].x, 0.125f * rp.z, rp.x), Wf, -0.5f);
        const float py = fmaf(fmaf(off[it].y, 0.125f * rp.w, rp.y), Wf, -0.5f);
        const float fx0 = floorf(px), fy0 = floorf(py);
        const float fx = px - fx0,    fy = py - fy0;
        const int x0 = (int)fx0, y0 = (int)fy0;

        const float gx = 1.f - fx, gy = 1.f - fy;
        const float w00 = ap[it] * gx * gy;
        const float w10 = ap[it] * fx * gy;
        const float w01 = ap[it] * gx * fy;
        const float w11 = ap[it] * fx * fy;

        const bool xin0 = (unsigned)x0       < (unsigned)W;
        const bool xin1 = (unsigned)(x0 + 1) < (unsigned)W;
        const bool yin0 = (unsigned)y0       < (unsigned)W;   // H == W
        const bool yin1 = (unsigned)(y0 + 1) < (unsigned)W;

        const float* vl = vb + (ptrdiff_t)cVS[it] * EMBED
                             + (ptrdiff_t)(y0 * W + x0) * EMBED;

        float4 v00 = make_float4(0.f,0.f,0.f,0.f);
        float4 v10 = v00, v01 = v00, v11 = v00;
        if (xin0 && yin0) v00 = *reinterpret_cast<const float4*>(vl);
        if (xin1 && yin0) v10 = *reinterpret_cast<const float4*>(vl + EMBED);
        if (xin0 && yin1) v01 = *reinterpret_cast<const float4*>(vl + W * EMBED);
        if (xin1 && yin1) v11 = *reinterpret_cast<const float4*>(vl + W * EMBED + EMBED);

        float4& acc = (it & 1) ? acc1 : acc0;
        acc.x = fmaf(w00, v00.x, fmaf(w10, v10.x, fmaf(w01, v01.x, fmaf(w11, v11.x, acc.x))));
        acc.y = fmaf(w00, v00.y, fmaf(w10, v10.y, fmaf(w01, v01.y, fmaf(w11, v11.y, acc.y))));
        acc.z = fmaf(w00, v00.z, fmaf(w10, v10.z, fmaf(w01, v01.z, fmaf(w11, v11.z, acc.z))));
        acc.w = fmaf(w00, v00.w, fmaf(w10, v10.w, fmaf(w01, v01.w, fmaf(w11, v11.w, acc.w))));
    }

    float4 acc;
    acc.x = acc0.x + acc1.x;
    acc.y = acc0.y + acc1.y;
    acc.z = acc0.z + acc1.z;
    acc.w = acc0.w + acc1.w;

    // ---- reduce over the 4 point-slots (lanes xor 8 and 16) ----
    #pragma unroll
    for (int o = 8; o <= 16; o <<= 1) {
        acc.x += __shfl_xor_sync(0xffffffffu, acc.x, o);
        acc.y += __shfl_xor_sync(0xffffffffu, acc.y, o);
        acc.z += __shfl_xor_sync(0xffffffffu, acc.z, o);
        acc.w += __shfl_xor_sync(0xffffffffu, acc.w, o);
    }

    if (psub == 0) {
        *reinterpret_cast<float4*>(out + (size_t)row * EMBED + h * HDIM + dgrp * 4) = acc;
    }
}

// ---------------- launch ----------------
extern "C" void kernel_launch(void* const* d_in, const int* in_sizes, int n_in,
                              void* d_out, int out_size)
{
    const float* query = (const float*)d_in[0];
    const float* refp  = (const float*)d_in[1];
    const float* value = (const float*)d_in[2];
    // d_in[3] = value_spatial_shapes (int64) — hardcoded
    const float* Woff  = (const float*)d_in[4];
    const float* boff  = (const float*)d_in[5];
    const float* Wattn = (const float*)d_in[6];
    const float* battn = (const float*)d_in[7];
    float* out = (float*)d_out;

    dim3 g(NROWS / BM, NLOGIT / BN);   // (250, 3)
    gemm_kernel<<<g, 128>>>(query, Woff, Wattn, boff, battn);

    sample_kernel<<<(BS_ * NHEADS * LQ_) / 8, 256>>>(value, refp, out);
}

// round 7
// speedup vs baseline: 1.2542x; 1.1445x over previous
#include <cuda_runtime.h>
#include <cuda_bf16.h>
#include <cstdint>
#include <math.h>

// ---------------- problem constants ----------------
#define BS_      16
#define LQ_      1000
#define NROWS    (BS_*LQ_)         // 16000
#define EMBED    256
#define NHEADS   8
#define HDIM     32
#define NLOGIT   384               // 256 offset cols + 128 attn-prob cols
#define LV_      13294

__device__ float g_logits[NROWS * NLOGIT];      // off(256) | softmaxed attn(128)
__device__ __nv_bfloat16 g_ahi[NROWS * EMBED];  // A split-hi  [row][k]
__device__ __nv_bfloat16 g_alo[NROWS * EMBED];  // A split-lo
__device__ __nv_bfloat16 g_bhi[NLOGIT * EMBED]; // B^T split-hi [n][k]
__device__ __nv_bfloat16 g_blo[NLOGIT * EMBED]; // B^T split-lo

// ======================= helpers =======================
__device__ __forceinline__ uint32_t smem_u32(const void* p) {
    uint32_t a;
    asm("{ .reg .u64 t; cvta.to.shared.u64 t, %1; cvt.u32.u64 %0, t; }" : "=r"(a) : "l"(p));
    return a;
}

__device__ __forceinline__ void ldsm4(uint32_t& r0, uint32_t& r1, uint32_t& r2, uint32_t& r3,
                                      uint32_t addr) {
    asm volatile("ldmatrix.sync.aligned.m8n8.x4.shared.b16 {%0,%1,%2,%3}, [%4];"
                 : "=r"(r0), "=r"(r1), "=r"(r2), "=r"(r3) : "r"(addr));
}

__device__ __forceinline__ void mma16816(float* c, const uint32_t* a, const uint32_t* b) {
    asm volatile(
        "mma.sync.aligned.m16n8k16.row.col.f32.bf16.bf16.f32 "
        "{%0,%1,%2,%3}, {%4,%5,%6,%7}, {%8,%9}, {%0,%1,%2,%3};"
        : "+f"(c[0]), "+f"(c[1]), "+f"(c[2]), "+f"(c[3])
        : "r"(a[0]), "r"(a[1]), "r"(a[2]), "r"(a[3]), "r"(b[0]), "r"(b[1]));
}

__device__ __forceinline__ uint32_t pack_bf2(__nv_bfloat16 a, __nv_bfloat16 b) {
    return (uint32_t)__bfloat16_as_ushort(a) | ((uint32_t)__bfloat16_as_ushort(b) << 16);
}

// ======================= conversion kernels =======================
__global__ __launch_bounds__(256)
void conv_a_kernel(const float* __restrict__ q)
{
    const size_t i = ((size_t)blockIdx.x * 256 + threadIdx.x) * 8;
    float4 v0 = __ldg(reinterpret_cast<const float4*>(q + i));
    float4 v1 = __ldg(reinterpret_cast<const float4*>(q + i + 4));
    float v[8] = {v0.x, v0.y, v0.z, v0.w, v1.x, v1.y, v1.z, v1.w};
    __nv_bfloat16 hi[8], lo[8];
    #pragma unroll
    for (int j = 0; j < 8; j++) {
        hi[j] = __float2bfloat16(v[j]);
        lo[j] = __float2bfloat16(v[j] - __bfloat162float(hi[j]));
    }
    uint4 uh, ul;
    uh.x = pack_bf2(hi[0], hi[1]); uh.y = pack_bf2(hi[2], hi[3]);
    uh.z = pack_bf2(hi[4], hi[5]); uh.w = pack_bf2(hi[6], hi[7]);
    ul.x = pack_bf2(lo[0], lo[1]); ul.y = pack_bf2(lo[2], lo[3]);
    ul.z = pack_bf2(lo[4], lo[5]); ul.w = pack_bf2(lo[6], lo[7]);
    *reinterpret_cast<uint4*>(g_ahi + i) = uh;
    *reinterpret_cast<uint4*>(g_alo + i) = ul;
}

__global__ __launch_bounds__(256)
void conv_b_kernel(const float* __restrict__ Woff, const float* __restrict__ Wattn)
{
    const int n = blockIdx.x;    // 0..383 (output column = B^T row)
    const int k = threadIdx.x;   // 0..255
    float x = (n < 256) ? __ldg(Woff + (size_t)k * 256 + n)
                        : __ldg(Wattn + (size_t)k * 128 + (n - 256));
    __nv_bfloat16 h = __float2bfloat16(x);
    g_bhi[(size_t)n * EMBED + k] = h;
    g_blo[(size_t)n * EMBED + k] = __float2bfloat16(x - __bfloat162float(h));
}

// ======================= mma.sync GEMM kernel =======================
// C[16000,384] = A @ B^T via split-bf16 (Ah*Bh + Ah*Bl + Al*Bh), fp32 acc.
// grid (125, 3): CTA tile 128(M) x 128(N), K = 256 chunked 4 x 64.
// 8 warps, each owns 32(M) x 64(N) = 2 x 8 m16n8k16 tiles.
// Epilogue: D -> smem -> +bias (+ per-head softmax for bn==2) -> g_logits.

#define LDA   72                 // bf16 smem stride (padded)
#define A_HI  0
#define A_LO  18432              // 128*72*2
#define B_HI  36864
#define B_LO  55296
#define SMT   73728
#define LDD   132                // f32 stride of reused D tile

__global__ __launch_bounds__(256)
void mma_gemm_kernel(const float* __restrict__ boff, const float* __restrict__ battn)
{
    extern __shared__ char smem[];
    const int tid  = threadIdx.x;
    const int wid  = tid >> 5;
    const int lane = tid & 31;
    const int bn   = blockIdx.y;            // 0..2
    const int rowg = blockIdx.x * 128;
    const uint32_t sb = smem_u32(smem);

    const int warp_m = (wid >> 1) * 32;     // 0,32,64,96
    const int warp_n = (wid & 1) * 64;      // 0,64

    float acc[2][8][4];
    #pragma unroll
    for (int mi = 0; mi < 2; mi++)
        #pragma unroll
        for (int nj = 0; nj < 8; nj++)
            #pragma unroll
            for (int c = 0; c < 4; c++) acc[mi][nj][c] = 0.f;

    for (int kc = 0; kc < 4; kc++) {
        const int k0 = kc * 64;
        __syncthreads();
        // stage A/B hi+lo for this k chunk: each region 128 rows x 64 bf16
        #pragma unroll
        for (int r = 0; r < 4; r++) {
            const int s = tid + r * 256;        // 0..1023
            const int row = s >> 3, j = s & 7;
            const uint32_t doff = (uint32_t)(row * LDA + j * 8) * 2;
            const size_t asrc = (size_t)(rowg + row) * EMBED + k0 + j * 8;
            const size_t bsrc = (size_t)(bn * 128 + row) * EMBED + k0 + j * 8;
            *reinterpret_cast<uint4*>(smem + A_HI + doff) = *reinterpret_cast<const uint4*>(g_ahi + asrc);
            *reinterpret_cast<uint4*>(smem + A_LO + doff) = *reinterpret_cast<const uint4*>(g_alo + asrc);
            *reinterpret_cast<uint4*>(smem + B_HI + doff) = *reinterpret_cast<const uint4*>(g_bhi + bsrc);
            *reinterpret_cast<uint4*>(smem + B_LO + doff) = *reinterpret_cast<const uint4*>(g_blo + bsrc);
        }
        __syncthreads();

        #pragma unroll
        for (int ks = 0; ks < 4; ks++) {
            const int kk = ks * 16;

            uint32_t ah[2][4], al[2][4];
            const int ar = warp_m + (lane & 15);
            const int ac = kk + ((lane >> 4) << 3);
            #pragma unroll
            for (int mi = 0; mi < 2; mi++) {
                const uint32_t ad = sb + A_HI + (uint32_t)(((ar + mi * 16) * LDA + ac) << 1);
                ldsm4(ah[mi][0], ah[mi][1], ah[mi][2], ah[mi][3], ad);
                ldsm4(al[mi][0], al[mi][1], al[mi][2], al[mi][3], ad + (A_LO - A_HI));
            }

            uint32_t bhf[4][4], blf[4][4];
            const int br = warp_n + (lane & 7) + ((lane >> 4) << 3);
            const int bc = kk + (((lane >> 3) & 1) << 3);
            #pragma unroll
            for (int g = 0; g < 4; g++) {
                const uint32_t bd = sb + B_HI + (uint32_t)(((br + g * 16) * LDA + bc) << 1);
                ldsm4(bhf[g][0], bhf[g][1], bhf[g][2], bhf[g][3], bd);
                ldsm4(blf[g][0], blf[g][1], blf[g][2], blf[g][3], bd + (B_LO - B_HI));
            }

            #pragma unroll
            for (int mi = 0; mi < 2; mi++)
                #pragma unroll
                for (int nj = 0; nj < 8; nj++) {
                    const int g = nj >> 1, o = (nj & 1) * 2;
                    mma16816(acc[mi][nj], ah[mi], &bhf[g][o]);
                    mma16816(acc[mi][nj], ah[mi], &blf[g][o]);
                    mma16816(acc[mi][nj], al[mi], &bhf[g][o]);
                }
        }
    }

    // ---- write accumulators to reused smem D tile ----
    __syncthreads();
    float* sD = reinterpret_cast<float*>(smem);   // [128][LDD]
    #pragma unroll
    for (int mi = 0; mi < 2; mi++)
        #pragma unroll
        for (int nj = 0; nj < 8; nj++) {
            const int r0 = warp_m + mi * 16 + (lane >> 2);
            const int c0 = warp_n + nj * 8 + (lane & 3) * 2;
            *reinterpret_cast<float2*>(sD + r0 * LDD + c0)       = make_float2(acc[mi][nj][0], acc[mi][nj][1]);
            *reinterpret_cast<float2*>(sD + (r0 + 8) * LDD + c0) = make_float2(acc[mi][nj][2], acc[mi][nj][3]);
        }
    __syncthreads();

    // ---- epilogue: bias (+softmax for attn block) -> g_logits ----
    const int row = tid >> 1;
    const int cp  = (tid & 1) * 64;
    float* orow = g_logits + (size_t)(rowg + row) * NLOGIT + bn * 128 + cp;

    #pragma unroll
    for (int g4 = 0; g4 < 4; g4++) {
        float f[16];
        #pragma unroll
        for (int j = 0; j < 16; j++) {
            const int c = cp + g4 * 16 + j;
            const float bias = (bn < 2) ? __ldg(boff + bn * 128 + c) : __ldg(battn + c);
            f[j] = sD[row * LDD + c] + bias;
        }
        if (bn == 2) {
            float mx = f[0];
            #pragma unroll
            for (int j = 1; j < 16; j++) mx = fmaxf(mx, f[j]);
            float s = 0.f;
            #pragma unroll
            for (int j = 0; j < 16; j++) { f[j] = __expf(f[j] - mx); s += f[j]; }
            const float rs = __fdividef(1.f, s);
            #pragma unroll
            for (int j = 0; j < 16; j++) f[j] *= rs;
        }
        #pragma unroll
        for (int j = 0; j < 16; j += 4)
            *reinterpret_cast<float4*>(orow + g4 * 16 + j) = make_float4(f[j], f[j+1], f[j+2], f[j+3]);
    }
}

// ---------------- Kernel B: bilinear sampling (unchanged from R5) ----------------
__global__ __launch_bounds__(256, 6)
void sample_kernel(const float* __restrict__ value,
                   const float* __restrict__ refp,
                   float* __restrict__ out)
{
    constexpr int cW[4]  = {100, 50, 25, 13};
    constexpr int cVS[4] = {0, 10000, 12500, 13125};

    const int warp = (blockIdx.x << 3) + (threadIdx.x >> 5);
    const int lane = threadIdx.x & 31;

    const int q  = warp % LQ_;
    const int bh = warp / LQ_;
    const int b  = bh >> 3;
    const int h  = bh & 7;
    const int row = b * LQ_ + q;

    const float* lg = g_logits + (size_t)row * NLOGIT;
    const float4 rp = __ldg(reinterpret_cast<const float4*>(refp) + row);

    const int psub = lane >> 3;
    const int dgrp = lane & 7;

    const float2* offp = reinterpret_cast<const float2*>(lg) + h * 16 + psub;
    const float*  app  = lg + 256 + h * 16 + psub;

    float2 off[4];
    float  ap[4];
    #pragma unroll
    for (int it = 0; it < 4; it++) {
        off[it] = __ldg(offp + (it << 2));
        ap[it]  = __ldg(app  + (it << 2));
    }

    const float* vb = value + (size_t)b * LV_ * EMBED + h * HDIM + dgrp * 4;

    float4 acc0 = make_float4(0.f, 0.f, 0.f, 0.f);
    float4 acc1 = acc0;

    #pragma unroll
    for (int it = 0; it < 4; it++) {
        const int   W  = cW[it];
        const float Wf = (float)W;

        const float px = fmaf(fmaf(off[it].x, 0.125f * rp.z, rp.x), Wf, -0.5f);
        const float py = fmaf(fmaf(off[it].y, 0.125f * rp.w, rp.y), Wf, -0.5f);
        const float fx0 = floorf(px), fy0 = floorf(py);
        const float fx = px - fx0,    fy = py - fy0;
        const int x0 = (int)fx0, y0 = (int)fy0;

        const float gx = 1.f - fx, gy = 1.f - fy;
        const float w00 = ap[it] * gx * gy;
        const float w10 = ap[it] * fx * gy;
        const float w01 = ap[it] * gx * fy;
        const float w11 = ap[it] * fx * fy;

        const bool xin0 = (unsigned)x0       < (unsigned)W;
        const bool xin1 = (unsigned)(x0 + 1) < (unsigned)W;
        const bool yin0 = (unsigned)y0       < (unsigned)W;
        const bool yin1 = (unsigned)(y0 + 1) < (unsigned)W;

        const float* vl = vb + (ptrdiff_t)cVS[it] * EMBED
                             + (ptrdiff_t)(y0 * W + x0) * EMBED;

        float4 v00 = make_float4(0.f,0.f,0.f,0.f);
        float4 v10 = v00, v01 = v00, v11 = v00;
        if (xin0 && yin0) v00 = *reinterpret_cast<const float4*>(vl);
        if (xin1 && yin0) v10 = *reinterpret_cast<const float4*>(vl + EMBED);
        if (xin0 && yin1) v01 = *reinterpret_cast<const float4*>(vl + W * EMBED);
        if (xin1 && yin1) v11 = *reinterpret_cast<const float4*>(vl + W * EMBED + EMBED);

        float4& acc = (it & 1) ? acc1 : acc0;
        acc.x = fmaf(w00, v00.x, fmaf(w10, v10.x, fmaf(w01, v01.x, fmaf(w11, v11.x, acc.x))));
        acc.y = fmaf(w00, v00.y, fmaf(w10, v10.y, fmaf(w01, v01.y, fmaf(w11, v11.y, acc.y))));
        acc.z = fmaf(w00, v00.z, fmaf(w10, v10.z, fmaf(w01, v01.z, fmaf(w11, v11.z, acc.z))));
        acc.w = fmaf(w00, v00.w, fmaf(w10, v10.w, fmaf(w01, v01.w, fmaf(w11, v11.w, acc.w))));
    }

    float4 acc;
    acc.x = acc0.x + acc1.x;
    acc.y = acc0.y + acc1.y;
    acc.z = acc0.z + acc1.z;
    acc.w = acc0.w + acc1.w;

    #pragma unroll
    for (int o = 8; o <= 16; o <<= 1) {
        acc.x += __shfl_xor_sync(0xffffffffu, acc.x, o);
        acc.y += __shfl_xor_sync(0xffffffffu, acc.y, o);
        acc.z += __shfl_xor_sync(0xffffffffu, acc.z, o);
        acc.w += __shfl_xor_sync(0xffffffffu, acc.w, o);
    }

    if (psub == 0) {
        *reinterpret_cast<float4*>(out + (size_t)row * EMBED + h * HDIM + dgrp * 4) = acc;
    }
}

// ---------------- launch ----------------
extern "C" void kernel_launch(void* const* d_in, const int* in_sizes, int n_in,
                              void* d_out, int out_size)
{
    (void)in_sizes; (void)n_in; (void)out_size;
    const float* query = (const float*)d_in[0];
    const float* refp  = (const float*)d_in[1];
    const float* value = (const float*)d_in[2];
    // d_in[3] = value_spatial_shapes (int64) — hardcoded
    const float* Woff  = (const float*)d_in[4];
    const float* boff  = (const float*)d_in[5];
    const float* Wattn = (const float*)d_in[6];
    const float* battn = (const float*)d_in[7];
    float* out = (float*)d_out;

    static bool attr_set = false;
    if (!attr_set) {
        cudaFuncSetAttribute(mma_gemm_kernel,
                             cudaFuncAttributeMaxDynamicSharedMemorySize, SMT);
        attr_set = true;
    }

    conv_a_kernel<<<(NROWS * EMBED / 8) / 256, 256>>>(query);       // 2000 blocks
    conv_b_kernel<<<NLOGIT, 256>>>(Woff, Wattn);                    // 384 blocks
    mma_gemm_kernel<<<dim3(NROWS / 128, 3), 256, SMT>>>(boff, battn);

    sample_kernel<<<(BS_ * NHEADS * LQ_) / 8, 256>>>(value, refp, out);
}